// round 12
// baseline (speedup 1.0000x reference)
#include <cuda_runtime.h>
#include <cstdint>

#define HH 1536
#define WW 2048
#define NN (HH*WW)
#define WPR 64                  // 32-bit words per row
#define CAP 512                 // max dilated runs per row (min period 4 -> 2048/4)
#define NSLOT (HH*CAP)
#define NBLK 148
#define NTHR 256
#define TOT (NBLK*NTHR)         // 37888 (divisible by 32)
#define NWARP (NBLK*8)          // 1184 warps

// scratch (device globals: allocation-free rule)
__device__ uint32_t g_comb[HH * WPR];   // comb bitmap
__device__ uint32_t g_text[HH * WPR];   // text bitmap
__device__ int g_rse[NSLOT];            // run xs | xe<<16
__device__ int g_runcnt[HH];
__device__ int g_rpar[NSLOT];           // min-ordered union-find over run slots
__device__ int g_rxmin[NSLOT];
__device__ int g_rxmax[NSLOT];
__device__ int g_rymax[NSLOT];
__device__ int g_rtext[NSLOT];
__device__ int g_bar[8];                // grid-barrier counters (reset by k_init)

__global__ void k_init() { if (threadIdx.x < 8) g_bar[threadIdx.x] = 0; }

// software grid barrier: all NBLK blocks co-resident (1 block/SM, 148 <= 152 SMs)
__device__ __forceinline__ void gbar(int slot) {
    __syncthreads();
    if (threadIdx.x == 0) {
        __threadfence();
        atomicAdd(&g_bar[slot], 1);
        volatile int* p = &g_bar[slot];
        while (*p < NBLK) { }
        __threadfence();
    }
    __syncthreads();
}

// concurrent min-union-find: parent[i] <= i, stays in-component; all writes
// are atomicMin (unions AND halving) -> race-free; root = component min slot.
__device__ __forceinline__ int uf_find(int i) {
    int n = __ldcg(&g_rpar[i]);
    while (n != i) {
        int g = __ldcg(&g_rpar[n]);
        if (g != n) atomicMin(&g_rpar[i], g);   // halve
        i = n; n = g;
    }
    return i;
}
__device__ __forceinline__ void uf_union(int a, int b) {
    while (true) {
        a = uf_find(a);
        b = uf_find(b);
        if (a == b) return;
        int lo = min(a, b), hi = max(a, b);
        int old = atomicMin(&g_rpar[hi], lo);
        if (old == hi) return;
        a = lo; b = old;
    }
}

__global__ void __launch_bounds__(NTHR, 1) k_main(const float* __restrict__ x,
                                                  float* __restrict__ out,
                                                  int n4, int out_size) {
    __shared__ uint16_t sstart[8][CAP];
    __shared__ uint16_t send_[8][CAP];
    __shared__ uint32_t stw[8][WPR];

    const unsigned FULL = 0xffffffffu;
    int tid = threadIdx.x;
    int gtid = blockIdx.x * NTHR + tid;
    int wid = tid >> 5, lane = tid & 31;
    int gwarp = blockIdx.x * 8 + wid;

    // ---- phase 0: zero output + build bitmaps ----
    float4 z4 = make_float4(0.f, 0.f, 0.f, 0.f);
    for (int i = gtid; i < n4; i += TOT) ((float4*)out)[i] = z4;
    for (int i = n4 * 4 + gtid; i < out_size; i += TOT) out[i] = 0.f;
    const float2* x2 = (const float2*)x;
    for (int i = gtid; i < NN; i += TOT) {     // NN%32==0, TOT%32==0 -> warp-uniform
        float2 p = x2[i];
        unsigned cb = __ballot_sync(FULL, (p.x > 0.4f) | (p.y > 0.4f));
        unsigned tb = __ballot_sync(FULL, p.x > 0.4f);
        if (lane == 0) { g_comb[i >> 5] = cb; g_text[i >> 5] = tb; }
    }
    gbar(0);

    // ---- phase 1: dilate (bit-smear) + parallel run extraction ----
    for (int y = gwarp; y < HH; y += NWARP) {
        const uint32_t* rc = &g_comb[y * WPR];
        uint32_t v0 = rc[lane], v1 = rc[32 + lane];
        if (y > 0)      { const uint32_t* r = &g_comb[(y - 1) * WPR]; v0 |= r[lane]; v1 |= r[32 + lane]; }
        if (y < HH - 1) { const uint32_t* r = &g_comb[(y + 1) * WPR]; v0 |= r[lane]; v1 |= r[32 + lane]; }
        stw[wid][lane]      = g_text[y * WPR + lane];
        stw[wid][32 + lane] = g_text[y * WPR + 32 + lane];

        // neighbor words of v (cross-word smear carries)
        uint32_t lv0 = __shfl_up_sync(FULL, v0, 1);   if (lane == 0)  lv0 = 0;
        uint32_t v0_31 = __shfl_sync(FULL, v0, 31);
        uint32_t lv1 = __shfl_up_sync(FULL, v1, 1);   if (lane == 0)  lv1 = v0_31;
        uint32_t rv0 = __shfl_down_sync(FULL, v0, 1);
        uint32_t v1_0 = __shfl_sync(FULL, v1, 0);
        if (lane == 31) rv0 = v1_0;
        uint32_t rv1 = __shfl_down_sync(FULL, v1, 1); if (lane == 31) rv1 = 0;

        uint32_t d0 = v0 | (v0 << 1) | (v0 >> 1) | (lv0 >> 31) | (rv0 << 31);
        uint32_t d1 = v1 | (v1 << 1) | (v1 >> 1) | (lv1 >> 31) | (rv1 << 31);

        // neighbor d for run start/end carries
        uint32_t ld0 = __shfl_up_sync(FULL, d0, 1);   if (lane == 0)  ld0 = 0;
        uint32_t d0_31 = __shfl_sync(FULL, d0, 31);
        uint32_t ld1 = __shfl_up_sync(FULL, d1, 1);   if (lane == 0)  ld1 = d0_31;
        uint32_t rd0 = __shfl_down_sync(FULL, d0, 1);
        uint32_t d1_0 = __shfl_sync(FULL, d1, 0);
        if (lane == 31) rd0 = d1_0;
        uint32_t rd1 = __shfl_down_sync(FULL, d1, 1); if (lane == 31) rd1 = 0;

        uint32_t s0 = d0 & ~((d0 << 1) | (ld0 >> 31));
        uint32_t s1 = d1 & ~((d1 << 1) | (ld1 >> 31));
        uint32_t e0 = d0 & ~((d0 >> 1) | (rd0 << 31));
        uint32_t e1 = d1 & ~((d1 >> 1) | (rd1 << 31));

        // packed warp scans: (start_count | end_count<<16), word order slot0 then slot1
        int pA = __popc(s0) | (__popc(e0) << 16);
        int pB = __popc(s1) | (__popc(e1) << 16);
        int iA = pA, iB = pB;
#pragma unroll
        for (int o = 1; o < 32; o <<= 1) {
            int t = __shfl_up_sync(FULL, iA, o); if (lane >= o) iA += t;
            t = __shfl_up_sync(FULL, iB, o);     if (lane >= o) iB += t;
        }
        int totA = __shfl_sync(FULL, iA, 31);
        int totB = __shfl_sync(FULL, iB, 31);
        int totS0 = totA & 0xffff, totE0 = totA >> 16;
        int baseS0 = (iA - pA) & 0xffff;
        int baseE0 = (iA - pA) >> 16;
        int baseS1 = totS0 + ((iB - pB) & 0xffff);
        int baseE1 = totE0 + ((iB - pB) >> 16);
        int cnt = totS0 + (totB & 0xffff);

        { uint32_t s = s0; int b2 = baseS0; while (s) { int b = __ffs(s) - 1; sstart[wid][b2++] = (uint16_t)(lane * 32 + b); s &= s - 1; } }
        { uint32_t s = s1; int b2 = baseS1; while (s) { int b = __ffs(s) - 1; sstart[wid][b2++] = (uint16_t)((32 + lane) * 32 + b); s &= s - 1; } }
        { uint32_t s = e0; int b2 = baseE0; while (s) { int b = __ffs(s) - 1; send_[wid][b2++] = (uint16_t)(lane * 32 + b); s &= s - 1; } }
        { uint32_t s = e1; int b2 = baseE1; while (s) { int b = __ffs(s) - 1; send_[wid][b2++] = (uint16_t)((32 + lane) * 32 + b); s &= s - 1; } }
        __syncwarp();

        if (lane == 0) g_runcnt[y] = cnt;
        for (int r = lane; r < cnt; r += 32) {
            int xs = sstart[wid][r], xe = send_[wid][r];
            int ws = xs >> 5, we = xe >> 5;
            unsigned acc = 0;
            for (int w = ws; w <= we; w++) {
                unsigned m = 0xffffffffu;
                if (w == ws) m &= (0xffffffffu << (xs & 31));
                if (w == we) { int hb = xe & 31; if (hb != 31) m &= (1u << (hb + 1)) - 1u; }
                acc |= stw[wid][w] & m;
            }
            int sid = y * CAP + r;
            g_rse[sid]   = xs | (xe << 16);
            g_rpar[sid]  = sid;
            g_rxmin[sid] = xs;
            g_rxmax[sid] = xe;
            g_rymax[sid] = y;
            g_rtext[sid] = (acc != 0);
        }
        __syncwarp();   // protect smem reuse on next sweep
    }
    gbar(1);

    // ---- phase 2: link overlapping runs of adjacent rows ----
    for (int y = gtid; y < HH - 1; y += TOT) {
        int ca = g_runcnt[y], cb = g_runcnt[y + 1];
        int i = 0, j = 0;
        int ab = y * CAP, bb = (y + 1) * CAP;
        while (i < ca && j < cb) {
            int A = g_rse[ab + i], B = g_rse[bb + j];
            int axs = A & 0xffff, axe = A >> 16;
            int bxs = B & 0xffff, bxe = B >> 16;
            if (axs <= bxe && bxs <= axe) uf_union(ab + i, bb + j);
            if (axe < bxe) i++; else j++;
        }
    }
    gbar(2);

    // ---- phase 3: fold run bboxes into final roots ----
    for (int y = gtid; y < HH; y += TOT) {
        int cnt = g_runcnt[y];
        for (int k = 0; k < cnt; k++) {
            int sid = y * CAP + k;
            int f = uf_find(sid);
            if (f == sid) continue;
            atomicMin(&g_rxmin[f], g_rxmin[sid]);
            atomicMax(&g_rxmax[f], g_rxmax[sid]);
            atomicMax(&g_rymax[f], g_rymax[sid]);
            if (g_rtext[sid]) atomicMax(&g_rtext[f], 1);
        }
    }
    gbar(3);

    // ---- phase 4: emit final roots ----
    for (int y = gtid; y < HH; y += TOT) {
        int cnt = g_runcnt[y];
        for (int k = 0; k < cnt; k++) {
            int sid = y * CAP + k;
            if (__ldcg(&g_rpar[sid]) != sid) continue;   // component root run
            int xs = g_rse[sid] & 0xffff;
            int flat = y * WW + xs;                       // component min flat index
            int h = g_rymax[sid] - y;
            int w = g_rxmax[sid] - g_rxmin[sid];
            if (h > 4 && w > 4 && g_rtext[sid]) {
                ((float4*)out)[flat] = make_float4((float)y, (float)g_rxmin[sid],
                                                   (float)h, (float)w);
                out[4 * NN + flat] = 1.0f;
            }
        }
    }
}

extern "C" void kernel_launch(void* const* d_in, const int* in_sizes, int n_in,
                              void* d_out, int out_size) {
    const float* x = (const float*)d_in[0];
    float* out = (float*)d_out;
    int n4 = out_size / 4;
    k_init<<<1, 32>>>();
    k_main<<<NBLK, NTHR>>>(x, out, n4, out_size);
}

// round 14
// speedup vs baseline: 1.1593x; 1.1593x over previous
#include <cuda_runtime.h>
#include <cstdint>

#define HH 1536
#define WW 2048
#define NN (HH*WW)
#define WPR 64                  // 32-bit words per row
#define CAP 512                 // max dilated runs per row (min period 4)
#define NSLOT (HH*CAP)
#define NBLK 148
#define NTHR 256
#define TOT (NBLK*NTHR)
#define NWARP (NBLK*8)

// scratch (device globals: allocation-free rule)
__device__ uint32_t g_comb[HH * WPR];   // comb bitmap
__device__ uint32_t g_text[HH * WPR];   // text bitmap
__device__ int g_rse[NSLOT];            // run xs | xe<<16
__device__ int g_runcnt[HH];
__device__ int g_rpar[NSLOT];           // min-ordered union-find over run slots
__device__ int g_rxmin[NSLOT];
__device__ int g_rxmax[NSLOT];
__device__ int g_rymax[NSLOT];
__device__ int g_rtext[NSLOT];
__device__ int g_bar[8];                // grid-barrier counters (reset in k_prep)

// software grid barrier: all NBLK blocks co-resident (1 block/SM, 148 <= 152 SMs)
__device__ __forceinline__ void gbar(int slot) {
    __syncthreads();
    if (threadIdx.x == 0) {
        __threadfence();
        atomicAdd(&g_bar[slot], 1);
        volatile int* p = &g_bar[slot];
        while (*p < NBLK) { }
        __threadfence();
    }
    __syncthreads();
}

// concurrent min-union-find: parent[i] <= i, stays in-component; all writes
// are atomicMin (unions AND halving) -> race-free; root = component min slot.
__device__ __forceinline__ int uf_find(int i) {
    int n = __ldcg(&g_rpar[i]);
    while (n != i) {
        int g = __ldcg(&g_rpar[n]);
        if (g != n) atomicMin(&g_rpar[i], g);   // halve
        i = n; n = g;
    }
    return i;
}
__device__ __forceinline__ void uf_union(int a, int b) {
    while (true) {
        a = uf_find(a);
        b = uf_find(b);
        if (a == b) return;
        int lo = min(a, b), hi = max(a, b);
        int old = atomicMin(&g_rpar[hi], lo);
        if (old == hi) return;
        a = lo; b = old;
    }
}

// ---------------- pass 1 (wide grid): zero output + bitmaps + barrier reset ----------------
__global__ void k_prep(const float* __restrict__ x, float* __restrict__ out,
                       int n4, int out_size) {
    int gid = blockIdx.x * blockDim.x + threadIdx.x;
    if (gid < 8) g_bar[gid] = 0;
    if (gid < n4) ((float4*)out)[gid] = make_float4(0.f, 0.f, 0.f, 0.f);
    int base = n4 * 4 + gid;
    if (base < out_size) out[base] = 0.f;        // tail (normally empty)
    if (gid < NN) {
        float2 p = ((const float2*)x)[gid];
        unsigned cb = __ballot_sync(0xffffffffu, (p.x > 0.4f) | (p.y > 0.4f));
        unsigned tb = __ballot_sync(0xffffffffu, p.x > 0.4f);
        if ((threadIdx.x & 31) == 0) {
            g_comb[gid >> 5] = cb;
            g_text[gid >> 5] = tb;
        }
    }
}

// ---------------- pass 2 (persistent): extract + link + fold + emit ----------------
__global__ void __launch_bounds__(NTHR, 1) k_rest(float* __restrict__ out) {
    __shared__ uint16_t sstart[8][CAP];
    __shared__ uint16_t send_[8][CAP];
    __shared__ uint32_t stw[8][WPR];

    const unsigned FULL = 0xffffffffu;
    int tid = threadIdx.x;
    int gtid = blockIdx.x * NTHR + tid;
    int wid = tid >> 5, lane = tid & 31;
    int gwarp = blockIdx.x * 8 + wid;

    // ---- phase 1: dilate (bit-smear) + parallel run extraction ----
    for (int y = gwarp; y < HH; y += NWARP) {
        const uint32_t* rc = &g_comb[y * WPR];
        uint32_t v0 = rc[lane], v1 = rc[32 + lane];
        if (y > 0)      { const uint32_t* r = &g_comb[(y - 1) * WPR]; v0 |= r[lane]; v1 |= r[32 + lane]; }
        if (y < HH - 1) { const uint32_t* r = &g_comb[(y + 1) * WPR]; v0 |= r[lane]; v1 |= r[32 + lane]; }
        stw[wid][lane]      = g_text[y * WPR + lane];
        stw[wid][32 + lane] = g_text[y * WPR + 32 + lane];

        // neighbor words of v (cross-word smear carries)
        uint32_t lv0 = __shfl_up_sync(FULL, v0, 1);   if (lane == 0)  lv0 = 0;
        uint32_t v0_31 = __shfl_sync(FULL, v0, 31);
        uint32_t lv1 = __shfl_up_sync(FULL, v1, 1);   if (lane == 0)  lv1 = v0_31;
        uint32_t rv0 = __shfl_down_sync(FULL, v0, 1);
        uint32_t v1_0 = __shfl_sync(FULL, v1, 0);
        if (lane == 31) rv0 = v1_0;
        uint32_t rv1 = __shfl_down_sync(FULL, v1, 1); if (lane == 31) rv1 = 0;

        uint32_t d0 = v0 | (v0 << 1) | (v0 >> 1) | (lv0 >> 31) | (rv0 << 31);
        uint32_t d1 = v1 | (v1 << 1) | (v1 >> 1) | (lv1 >> 31) | (rv1 << 31);

        // neighbor d for run start/end carries
        uint32_t ld0 = __shfl_up_sync(FULL, d0, 1);   if (lane == 0)  ld0 = 0;
        uint32_t d0_31 = __shfl_sync(FULL, d0, 31);
        uint32_t ld1 = __shfl_up_sync(FULL, d1, 1);   if (lane == 0)  ld1 = d0_31;
        uint32_t rd0 = __shfl_down_sync(FULL, d0, 1);
        uint32_t d1_0 = __shfl_sync(FULL, d1, 0);
        if (lane == 31) rd0 = d1_0;
        uint32_t rd1 = __shfl_down_sync(FULL, d1, 1); if (lane == 31) rd1 = 0;

        uint32_t s0 = d0 & ~((d0 << 1) | (ld0 >> 31));
        uint32_t s1 = d1 & ~((d1 << 1) | (ld1 >> 31));
        uint32_t e0 = d0 & ~((d0 >> 1) | (rd0 << 31));
        uint32_t e1 = d1 & ~((d1 >> 1) | (rd1 << 31));

        // packed warp scans: (start_count | end_count<<16)
        int pA = __popc(s0) | (__popc(e0) << 16);
        int pB = __popc(s1) | (__popc(e1) << 16);
        int iA = pA, iB = pB;
#pragma unroll
        for (int o = 1; o < 32; o <<= 1) {
            int t = __shfl_up_sync(FULL, iA, o); if (lane >= o) iA += t;
            t = __shfl_up_sync(FULL, iB, o);     if (lane >= o) iB += t;
        }
        int totA = __shfl_sync(FULL, iA, 31);
        int totB = __shfl_sync(FULL, iB, 31);
        int totS0 = totA & 0xffff, totE0 = totA >> 16;
        int baseS0 = (iA - pA) & 0xffff;
        int baseE0 = (iA - pA) >> 16;
        int baseS1 = totS0 + ((iB - pB) & 0xffff);
        int baseE1 = totE0 + ((iB - pB) >> 16);
        int cnt = totS0 + (totB & 0xffff);

        { uint32_t s = s0; int b2 = baseS0; while (s) { int b = __ffs(s) - 1; sstart[wid][b2++] = (uint16_t)(lane * 32 + b); s &= s - 1; } }
        { uint32_t s = s1; int b2 = baseS1; while (s) { int b = __ffs(s) - 1; sstart[wid][b2++] = (uint16_t)((32 + lane) * 32 + b); s &= s - 1; } }
        { uint32_t s = e0; int b2 = baseE0; while (s) { int b = __ffs(s) - 1; send_[wid][b2++] = (uint16_t)(lane * 32 + b); s &= s - 1; } }
        { uint32_t s = e1; int b2 = baseE1; while (s) { int b = __ffs(s) - 1; send_[wid][b2++] = (uint16_t)((32 + lane) * 32 + b); s &= s - 1; } }
        __syncwarp();

        if (lane == 0) g_runcnt[y] = cnt;
        for (int r = lane; r < cnt; r += 32) {
            int xs = sstart[wid][r], xe = send_[wid][r];
            int ws = xs >> 5, we = xe >> 5;
            unsigned acc = 0;
            for (int w = ws; w <= we; w++) {
                unsigned m = 0xffffffffu;
                if (w == ws) m &= (0xffffffffu << (xs & 31));
                if (w == we) { int hb = xe & 31; if (hb != 31) m &= (1u << (hb + 1)) - 1u; }
                acc |= stw[wid][w] & m;
            }
            int sid = y * CAP + r;
            g_rse[sid]   = xs | (xe << 16);
            g_rpar[sid]  = sid;
            g_rxmin[sid] = xs;
            g_rxmax[sid] = xe;
            g_rymax[sid] = y;
            g_rtext[sid] = (acc != 0);
        }
        __syncwarp();   // protect smem reuse on next sweep
    }
    gbar(0);

    // ---- phase 2: link overlapping runs of adjacent rows ----
    for (int y = gtid; y < HH - 1; y += TOT) {
        int ca = g_runcnt[y], cb = g_runcnt[y + 1];
        int i = 0, j = 0;
        int ab = y * CAP, bb = (y + 1) * CAP;
        while (i < ca && j < cb) {
            int A = g_rse[ab + i], B = g_rse[bb + j];
            int axs = A & 0xffff, axe = A >> 16;
            int bxs = B & 0xffff, bxe = B >> 16;
            if (axs <= bxe && bxs <= axe) uf_union(ab + i, bb + j);
            if (axe < bxe) i++; else j++;
        }
    }
    gbar(1);

    // ---- phase 3: fold run bboxes into final roots ----
    for (int y = gtid; y < HH; y += TOT) {
        int cnt = g_runcnt[y];
        for (int k = 0; k < cnt; k++) {
            int sid = y * CAP + k;
            int f = uf_find(sid);
            if (f == sid) continue;
            atomicMin(&g_rxmin[f], g_rxmin[sid]);
            atomicMax(&g_rxmax[f], g_rxmax[sid]);
            atomicMax(&g_rymax[f], g_rymax[sid]);
            if (g_rtext[sid]) atomicMax(&g_rtext[f], 1);
        }
    }
    gbar(2);

    // ---- phase 4: emit final roots ----
    for (int y = gtid; y < HH; y += TOT) {
        int cnt = g_runcnt[y];
        for (int k = 0; k < cnt; k++) {
            int sid = y * CAP + k;
            if (__ldcg(&g_rpar[sid]) != sid) continue;   // component root run
            int xs = g_rse[sid] & 0xffff;
            int flat = y * WW + xs;                       // component min flat index
            int h = g_rymax[sid] - y;
            int w = g_rxmax[sid] - g_rxmin[sid];
            if (h > 4 && w > 4 && g_rtext[sid]) {
                ((float4*)out)[flat] = make_float4((float)y, (float)g_rxmin[sid],
                                                   (float)h, (float)w);
                out[4 * NN + flat] = 1.0f;
            }
        }
    }
}

extern "C" void kernel_launch(void* const* d_in, const int* in_sizes, int n_in,
                              void* d_out, int out_size) {
    const float* x = (const float*)d_in[0];
    float* out = (float*)d_out;
    int n4 = out_size / 4;
    int nprep = (n4 > NN) ? n4 : NN;
    k_prep<<<(nprep + 255) / 256, 256>>>(x, out, n4, out_size);
    k_rest<<<NBLK, NTHR>>>(out);
}

// round 15
// speedup vs baseline: 1.4793x; 1.2761x over previous
#include <cuda_runtime.h>
#include <cstdint>

#define HH 1536
#define WW 2048
#define NN (HH*WW)
#define WPR 64                  // 32-bit words per row
#define CAP 512                 // max dilated runs per row (min period 4)
#define NSLOT (HH*CAP)
#define MAXC 8192               // compact run capacity (expected ~3100, >100 sigma margin)

// scratch (device globals: allocation-free rule)
__device__ uint32_t g_comb[HH * WPR];   // comb bitmap
__device__ uint32_t g_text[HH * WPR];   // text bitmap
__device__ int g_rse[NSLOT];            // run xs | xe<<16 (sid = y*CAP + k)
__device__ int g_rtext[NSLOT];          // run has-text flag
__device__ int g_runcnt[HH];
// compact (cid-indexed) arrays
__device__ int g_cxse[MAXC];
__device__ int g_cy[MAXC];
__device__ int g_ctext[MAXC];
__device__ int g_cxmin[MAXC];
__device__ int g_cxmax[MAXC];
__device__ int g_cymax[MAXC];

// ---------------- pass 1 (wide grid): zero output + build bitmaps ----------------
__global__ void k_prep(const float* __restrict__ x, float* __restrict__ out,
                       int n4, int out_size) {
    int gid = blockIdx.x * blockDim.x + threadIdx.x;
    if (gid < n4) ((float4*)out)[gid] = make_float4(0.f, 0.f, 0.f, 0.f);
    int base = n4 * 4 + gid;
    if (base < out_size) out[base] = 0.f;        // tail (normally empty)
    if (gid < NN) {
        float2 p = ((const float2*)x)[gid];
        unsigned cb = __ballot_sync(0xffffffffu, (p.x > 0.4f) | (p.y > 0.4f));
        unsigned tb = __ballot_sync(0xffffffffu, p.x > 0.4f);
        if ((threadIdx.x & 31) == 0) {
            g_comb[gid >> 5] = cb;
            g_text[gid >> 5] = tb;
        }
    }
}

// ---------------- pass 2 (wide grid): dilate + parallel run extraction ----------------
__global__ void __launch_bounds__(256) k_runs() {
    __shared__ uint16_t sstart[8][CAP];
    __shared__ uint16_t send_[8][CAP];
    __shared__ uint32_t stw[8][WPR];

    const unsigned FULL = 0xffffffffu;
    int tid = threadIdx.x;
    int wid = tid >> 5, lane = tid & 31;
    int y = blockIdx.x * 8 + wid;            // grid = HH/8 blocks

    const uint32_t* rc = &g_comb[y * WPR];
    uint32_t v0 = rc[lane], v1 = rc[32 + lane];
    if (y > 0)      { const uint32_t* r = &g_comb[(y - 1) * WPR]; v0 |= r[lane]; v1 |= r[32 + lane]; }
    if (y < HH - 1) { const uint32_t* r = &g_comb[(y + 1) * WPR]; v0 |= r[lane]; v1 |= r[32 + lane]; }
    stw[wid][lane]      = g_text[y * WPR + lane];
    stw[wid][32 + lane] = g_text[y * WPR + 32 + lane];

    // neighbor words of v (cross-word smear carries)
    uint32_t lv0 = __shfl_up_sync(FULL, v0, 1);   if (lane == 0)  lv0 = 0;
    uint32_t v0_31 = __shfl_sync(FULL, v0, 31);
    uint32_t lv1 = __shfl_up_sync(FULL, v1, 1);   if (lane == 0)  lv1 = v0_31;
    uint32_t rv0 = __shfl_down_sync(FULL, v0, 1);
    uint32_t v1_0 = __shfl_sync(FULL, v1, 0);
    if (lane == 31) rv0 = v1_0;
    uint32_t rv1 = __shfl_down_sync(FULL, v1, 1); if (lane == 31) rv1 = 0;

    uint32_t d0 = v0 | (v0 << 1) | (v0 >> 1) | (lv0 >> 31) | (rv0 << 31);
    uint32_t d1 = v1 | (v1 << 1) | (v1 >> 1) | (lv1 >> 31) | (rv1 << 31);

    // neighbor d for run start/end carries
    uint32_t ld0 = __shfl_up_sync(FULL, d0, 1);   if (lane == 0)  ld0 = 0;
    uint32_t d0_31 = __shfl_sync(FULL, d0, 31);
    uint32_t ld1 = __shfl_up_sync(FULL, d1, 1);   if (lane == 0)  ld1 = d0_31;
    uint32_t rd0 = __shfl_down_sync(FULL, d0, 1);
    uint32_t d1_0 = __shfl_sync(FULL, d1, 0);
    if (lane == 31) rd0 = d1_0;
    uint32_t rd1 = __shfl_down_sync(FULL, d1, 1); if (lane == 31) rd1 = 0;

    uint32_t s0 = d0 & ~((d0 << 1) | (ld0 >> 31));
    uint32_t s1 = d1 & ~((d1 << 1) | (ld1 >> 31));
    uint32_t e0 = d0 & ~((d0 >> 1) | (rd0 << 31));
    uint32_t e1 = d1 & ~((d1 >> 1) | (rd1 << 31));

    // packed warp scans: (start_count | end_count<<16)
    int pA = __popc(s0) | (__popc(e0) << 16);
    int pB = __popc(s1) | (__popc(e1) << 16);
    int iA = pA, iB = pB;
#pragma unroll
    for (int o = 1; o < 32; o <<= 1) {
        int t = __shfl_up_sync(FULL, iA, o); if (lane >= o) iA += t;
        t = __shfl_up_sync(FULL, iB, o);     if (lane >= o) iB += t;
    }
    int totA = __shfl_sync(FULL, iA, 31);
    int totB = __shfl_sync(FULL, iB, 31);
    int totS0 = totA & 0xffff, totE0 = totA >> 16;
    int baseS0 = (iA - pA) & 0xffff;
    int baseE0 = (iA - pA) >> 16;
    int baseS1 = totS0 + ((iB - pB) & 0xffff);
    int baseE1 = totE0 + ((iB - pB) >> 16);
    int cnt = totS0 + (totB & 0xffff);

    { uint32_t s = s0; int b2 = baseS0; while (s) { int b = __ffs(s) - 1; sstart[wid][b2++] = (uint16_t)(lane * 32 + b); s &= s - 1; } }
    { uint32_t s = s1; int b2 = baseS1; while (s) { int b = __ffs(s) - 1; sstart[wid][b2++] = (uint16_t)((32 + lane) * 32 + b); s &= s - 1; } }
    { uint32_t s = e0; int b2 = baseE0; while (s) { int b = __ffs(s) - 1; send_[wid][b2++] = (uint16_t)(lane * 32 + b); s &= s - 1; } }
    { uint32_t s = e1; int b2 = baseE1; while (s) { int b = __ffs(s) - 1; send_[wid][b2++] = (uint16_t)((32 + lane) * 32 + b); s &= s - 1; } }
    __syncwarp();

    if (lane == 0) g_runcnt[y] = cnt;
    for (int r = lane; r < cnt; r += 32) {
        int xs = sstart[wid][r], xe = send_[wid][r];
        int ws = xs >> 5, we = xe >> 5;
        unsigned acc = 0;
        for (int w = ws; w <= we; w++) {
            unsigned m = 0xffffffffu;
            if (w == ws) m &= (0xffffffffu << (xs & 31));
            if (w == we) { int hb = xe & 31; if (hb != 31) m &= (1u << (hb + 1)) - 1u; }
            acc |= stw[wid][w] & m;
        }
        int sid = y * CAP + r;
        g_rse[sid]   = xs | (xe << 16);
        g_rtext[sid] = (acc != 0);
    }
}

// ---------------- smem union-find (min-ordered, atomicMin halving) ----------------
__device__ __forceinline__ int sfind(int* L, int i) {
    int n = L[i];
    while (n != i) {
        int g2 = L[n];
        if (g2 != n) atomicMin(&L[i], g2);   // halve
        i = n; n = g2;
    }
    return i;
}
__device__ __forceinline__ void sunite(int* L, int a, int b) {
    while (true) {
        a = sfind(L, a);
        b = sfind(L, b);
        if (a == b) return;
        int lo = min(a, b), hi = max(a, b);
        int old = atomicMin(&L[hi], lo);
        if (old == hi) return;
        a = lo; b = old;
    }
}

// ---------------- pass 3 (single block): compact + hierarchical CCL + fold + emit ----------------
__global__ void __launch_bounds__(1024, 1) k_final(float* __restrict__ out) {
    __shared__ int spar[MAXC];      // 32 KB
    __shared__ int soff[2049];      // 8.2 KB: exclusive row offsets (padded scan)
    __shared__ int swt[32];

    const unsigned FULL = 0xffffffffu;
    int tid = threadIdx.x;
    int lane = tid & 31, warp = tid >> 5;

    // ---- scan of per-row run counts (2048-padded, 2 elems/thread) ----
    int e0 = 2 * tid, e1 = 2 * tid + 1;
    int c0 = (e0 < HH) ? g_runcnt[e0] : 0;
    int c1 = (e1 < HH) ? g_runcnt[e1] : 0;
    int s = c0 + c1;
    int incl = s;
#pragma unroll
    for (int o = 1; o < 32; o <<= 1) {
        int t = __shfl_up_sync(FULL, incl, o);
        if (lane >= o) incl += t;
    }
    if (lane == 31) swt[warp] = incl;
    __syncthreads();
    if (tid < 32) {
        int v = swt[tid], iv = v;
#pragma unroll
        for (int o = 1; o < 32; o <<= 1) {
            int t = __shfl_up_sync(FULL, iv, o);
            if (tid >= o) iv += t;
        }
        swt[tid] = iv - v;   // exclusive warp base
    }
    __syncthreads();
    int base = swt[warp] + incl - s;     // exclusive prefix for element e0
    soff[e0] = base;
    soff[e1] = base + c0;
    __syncthreads();

    int R = soff[HH];
    if (R > MAXC) R = MAXC;              // stats: ~3100 expected, cap is >100 sigma

    // ---- copy runs to compact arrays + init parents ----
    for (int y = tid; y < HH; y += 1024) {
        int off = soff[y], cnt = soff[y + 1] - off;
        for (int k = 0; k < cnt; k++) {
            int cid = off + k;
            if (cid >= MAXC) break;
            int sid = y * CAP + k;
            int se = g_rse[sid];
            g_cxse[cid]  = se;
            g_cy[cid]    = y;
            g_ctext[cid] = g_rtext[sid];
            g_cxmin[cid] = se & 0xffff;
            g_cxmax[cid] = se >> 16;
            g_cymax[cid] = y;
        }
    }
    for (int i = tid; i < R; i += 1024) spar[i] = i;
    __syncthreads();

    // ---- hierarchical union rounds: round r merges row-blocks of size 2^r ----
    // boundary b has unique decomposition b = (2m+1)<<r  -> each processed once,
    // tree depth stays O(log) so smem finds are ~2-3 hops.
#pragma unroll
    for (int r = 0; r < 11; r++) {
        for (int m = tid; ; m += 1024) {
            int b = (2 * m + 1) << r;
            if (b >= HH) break;
            int i = soff[b - 1], ie = soff[b];
            int j = soff[b],     je = soff[b + 1];
            if (ie > MAXC) ie = MAXC;
            if (je > MAXC) je = MAXC;
            while (i < ie && j < je) {
                int A = g_cxse[i], B = g_cxse[j];
                int axs = A & 0xffff, axe = A >> 16;
                int bxs = B & 0xffff, bxe = B >> 16;
                if (axs <= bxe && bxs <= axe) sunite(spar, i, j);
                if (axe < bxe) i++; else j++;
            }
        }
        __syncthreads();
    }

    // ---- full compress (no more unions: plain stores safe) ----
    for (int i = tid; i < R; i += 1024) {
        int f = i, n = spar[f];
        while (n != f) { f = n; n = spar[f]; }
        spar[i] = f;
    }
    __syncthreads();

    // ---- fold run bboxes into roots ----
    for (int i = tid; i < R; i += 1024) {
        int f = spar[i];
        if (f == i) continue;
        atomicMin(&g_cxmin[f], g_cxmin[i]);
        atomicMax(&g_cxmax[f], g_cxmax[i]);
        atomicMax(&g_cymax[f], g_cy[i]);
        if (g_ctext[i]) atomicMax(&g_ctext[f], 1);
    }
    __syncthreads();

    // ---- emit roots ----
    for (int i = tid; i < R; i += 1024) {
        if (spar[i] != i) continue;          // root = component min (y,k) run
        int y = g_cy[i];
        int xs = g_cxse[i] & 0xffff;         // min flat index = y*WW + xs
        int h = g_cymax[i] - y;
        int w = g_cxmax[i] - g_cxmin[i];
        if (h > 4 && w > 4 && g_ctext[i]) {
            int flat = y * WW + xs;
            ((float4*)out)[flat] = make_float4((float)y, (float)g_cxmin[i],
                                               (float)h, (float)w);
            out[4 * NN + flat] = 1.0f;
        }
    }
}

extern "C" void kernel_launch(void* const* d_in, const int* in_sizes, int n_in,
                              void* d_out, int out_size) {
    const float* x = (const float*)d_in[0];
    float* out = (float*)d_out;
    int n4 = out_size / 4;
    int nprep = (n4 > NN) ? n4 : NN;
    k_prep<<<(nprep + 255) / 256, 256>>>(x, out, n4, out_size);
    k_runs<<<HH / 8, 256>>>();
    k_final<<<1, 1024>>>(out);
}

// round 17
// speedup vs baseline: 1.4955x; 1.0109x over previous
#include <cuda_runtime.h>
#include <cstdint>

#define HH 1536
#define WW 2048
#define NN (HH*WW)
#define WPR 64                  // 32-bit words per row
#define CAP 512                 // max dilated runs per row
#define NSLOT (HH*CAP)
#define MAXC 8192               // compact run capacity (expected ~3100)
#define NBLK 148
#define NTHR 1024
#define GROUPS 192              // HH/8 row-groups
#define DYNSM 73760             // >= 65536 + 8196 (final view); extraction view ~21KB

// scratch (device globals: allocation-free rule)
__device__ int g_rse[NSLOT];            // run xs | xe<<16 (sid = y*CAP + k)
__device__ int g_rtext[NSLOT];
__device__ int g_runcnt[HH];
__device__ int g_cy[MAXC];
__device__ int g_ctext[MAXC];
__device__ int g_cxmin[MAXC];
__device__ int g_cxmax[MAXC];
__device__ int g_cymax[MAXC];
__device__ int g_bar;                   // arrival counter; block 0 resets after spin

// ---------------- smem union-find (min-ordered, atomicMin halving) ----------------
__device__ __forceinline__ int sfind(int* L, int i) {
    int n = L[i];
    while (n != i) {
        int g2 = L[n];
        if (g2 != n) atomicMin(&L[i], g2);   // halve
        i = n; n = g2;
    }
    return i;
}
__device__ __forceinline__ void sunite(int* L, int a, int b) {
    while (true) {
        a = sfind(L, a);
        b = sfind(L, b);
        if (a == b) return;
        int lo = min(a, b), hi = max(a, b);
        int old = atomicMin(&L[hi], lo);
        if (old == hi) return;
        a = lo; b = old;
    }
}

__global__ void __launch_bounds__(NTHR, 1) k_all(const float* __restrict__ x,
                                                 float* __restrict__ out,
                                                 int n4, int out_size) {
    extern __shared__ char dynsm[];
    __shared__ int swt[32];
    const unsigned FULL = 0xffffffffu;
    int tid = threadIdx.x, lane = tid & 31, wid = tid >> 5;

    // ---------------- zero output (grid-stride) ----------------
    float4 z4 = make_float4(0.f, 0.f, 0.f, 0.f);
    for (int i = blockIdx.x * NTHR + tid; i < n4; i += NBLK * NTHR)
        ((float4*)out)[i] = z4;
    for (int i = n4 * 4 + blockIdx.x * NTHR + tid; i < out_size; i += NBLK * NTHR)
        out[i] = 0.f;

    // extraction smem view
    uint32_t (*scomb)[WPR]  = (uint32_t(*)[WPR]) dynsm;                     // [10][64]
    uint32_t (*stext)[WPR]  = (uint32_t(*)[WPR])(dynsm + 10 * WPR * 4);     // [8][64]
    uint16_t (*sstart)[CAP] = (uint16_t(*)[CAP])(dynsm + 18 * WPR * 4);     // [8][512]
    uint16_t (*send_)[CAP]  = (uint16_t(*)[CAP])(dynsm + 18 * WPR * 4 + 8 * CAP * 2);

    const float2* x2 = (const float2*)x;

    // ---------------- per 8-row group: threshold -> smem bitmaps -> extract ----------------
    for (int g = blockIdx.x; g < GROUPS; g += NBLK) {
        int base = g * 8;
        __syncthreads();   // protect smem reuse across groups

        // 640 chunk-tasks (10 rows x 64 words), T = t*32 + wid, t in [0,20).
        // Batched preload (MLP=10) so ballots don't serialize on load latency.
#pragma unroll
        for (int t0 = 0; t0 < 20; t0 += 10) {
            float2 buf[10];
#pragma unroll
            for (int k = 0; k < 10; k++) {
                int T = (t0 + k) * 32 + wid;
                int r = T >> 6, c = T & 63;
                int y = base - 1 + r;
                buf[k] = (y >= 0 && y < HH) ? x2[y * WW + c * 32 + lane]
                                            : make_float2(0.f, 0.f);
            }
#pragma unroll
            for (int k = 0; k < 10; k++) {
                int T = (t0 + k) * 32 + wid;
                int r = T >> 6, c = T & 63;
                unsigned cb = __ballot_sync(FULL, (buf[k].x > 0.4f) | (buf[k].y > 0.4f));
                unsigned tb = __ballot_sync(FULL, buf[k].x > 0.4f);
                if (lane == 0) {
                    scomb[r][c] = cb;
                    if (r >= 1 && r <= 8) stext[r - 1][c] = tb;
                }
            }
        }
        __syncthreads();

        // extraction: warps 0-7 handle rows base..base+7 (proven R15 machinery)
        if (wid < 8) {
            int y = base + wid;
            uint32_t v0 = scomb[wid][lane]      | scomb[wid + 1][lane]      | scomb[wid + 2][lane];
            uint32_t v1 = scomb[wid][32 + lane] | scomb[wid + 1][32 + lane] | scomb[wid + 2][32 + lane];

            uint32_t lv0 = __shfl_up_sync(FULL, v0, 1);   if (lane == 0)  lv0 = 0;
            uint32_t v0_31 = __shfl_sync(FULL, v0, 31);
            uint32_t lv1 = __shfl_up_sync(FULL, v1, 1);   if (lane == 0)  lv1 = v0_31;
            uint32_t rv0 = __shfl_down_sync(FULL, v0, 1);
            uint32_t v1_0 = __shfl_sync(FULL, v1, 0);
            if (lane == 31) rv0 = v1_0;
            uint32_t rv1 = __shfl_down_sync(FULL, v1, 1); if (lane == 31) rv1 = 0;

            uint32_t d0 = v0 | (v0 << 1) | (v0 >> 1) | (lv0 >> 31) | (rv0 << 31);
            uint32_t d1 = v1 | (v1 << 1) | (v1 >> 1) | (lv1 >> 31) | (rv1 << 31);

            uint32_t ld0 = __shfl_up_sync(FULL, d0, 1);   if (lane == 0)  ld0 = 0;
            uint32_t d0_31 = __shfl_sync(FULL, d0, 31);
            uint32_t ld1 = __shfl_up_sync(FULL, d1, 1);   if (lane == 0)  ld1 = d0_31;
            uint32_t rd0 = __shfl_down_sync(FULL, d0, 1);
            uint32_t d1_0 = __shfl_sync(FULL, d1, 0);
            if (lane == 31) rd0 = d1_0;
            uint32_t rd1 = __shfl_down_sync(FULL, d1, 1); if (lane == 31) rd1 = 0;

            uint32_t s0 = d0 & ~((d0 << 1) | (ld0 >> 31));
            uint32_t s1 = d1 & ~((d1 << 1) | (ld1 >> 31));
            uint32_t e0 = d0 & ~((d0 >> 1) | (rd0 << 31));
            uint32_t e1 = d1 & ~((d1 >> 1) | (rd1 << 31));

            int pA = __popc(s0) | (__popc(e0) << 16);
            int pB = __popc(s1) | (__popc(e1) << 16);
            int iA = pA, iB = pB;
#pragma unroll
            for (int o = 1; o < 32; o <<= 1) {
                int t = __shfl_up_sync(FULL, iA, o); if (lane >= o) iA += t;
                t = __shfl_up_sync(FULL, iB, o);     if (lane >= o) iB += t;
            }
            int totA = __shfl_sync(FULL, iA, 31);
            int totB = __shfl_sync(FULL, iB, 31);
            int totS0 = totA & 0xffff, totE0 = totA >> 16;
            int baseS0 = (iA - pA) & 0xffff;
            int baseE0 = (iA - pA) >> 16;
            int baseS1 = totS0 + ((iB - pB) & 0xffff);
            int baseE1 = totE0 + ((iB - pB) >> 16);
            int cnt = totS0 + (totB & 0xffff);

            { uint32_t s = s0; int b2 = baseS0; while (s) { int b = __ffs(s) - 1; sstart[wid][b2++] = (uint16_t)(lane * 32 + b); s &= s - 1; } }
            { uint32_t s = s1; int b2 = baseS1; while (s) { int b = __ffs(s) - 1; sstart[wid][b2++] = (uint16_t)((32 + lane) * 32 + b); s &= s - 1; } }
            { uint32_t s = e0; int b2 = baseE0; while (s) { int b = __ffs(s) - 1; send_[wid][b2++] = (uint16_t)(lane * 32 + b); s &= s - 1; } }
            { uint32_t s = e1; int b2 = baseE1; while (s) { int b = __ffs(s) - 1; send_[wid][b2++] = (uint16_t)((32 + lane) * 32 + b); s &= s - 1; } }
            __syncwarp();

            if (lane == 0) g_runcnt[y] = cnt;
            for (int r = lane; r < cnt; r += 32) {
                int xs = sstart[wid][r], xe = send_[wid][r];
                int ws = xs >> 5, we = xe >> 5;
                unsigned acc = 0;
                for (int w = ws; w <= we; w++) {
                    unsigned m = 0xffffffffu;
                    if (w == ws) m &= (0xffffffffu << (xs & 31));
                    if (w == we) { int hb = xe & 31; if (hb != 31) m &= (1u << (hb + 1)) - 1u; }
                    acc |= stext[wid][w] & m;
                }
                int sid = y * CAP + r;
                g_rse[sid]   = xs | (xe << 16);
                g_rtext[sid] = (acc != 0);
            }
        }
    }
    __syncthreads();

    // ---------------- arrival barrier: only block 0 spins (deadlock-free) ----------------
    if (blockIdx.x != 0) {
        if (tid == 0) { __threadfence(); atomicAdd(&g_bar, 1); }
        return;
    }
    if (tid == 0) {
        __threadfence();
        atomicAdd(&g_bar, 1);
        volatile int* p = &g_bar;
        while (*p < NBLK) { }
        g_bar = 0;              // reset for next graph replay (only block 0 alive)
        __threadfence();
    }
    __syncthreads();

    // ---------------- finale (block 0, 1024 threads): compact + CCL + fold + emit ----------------
    int* spar = (int*)dynsm;               // [MAXC]
    int* cxse = (int*)(dynsm + 32768);     // [MAXC]
    int* soff = (int*)(dynsm + 65536);     // [2049]

    // scan of per-row run counts (2048-padded, 2 elems/thread)
    int e0 = 2 * tid, e1 = 2 * tid + 1;
    int c0 = (e0 < HH) ? g_runcnt[e0] : 0;
    int c1 = (e1 < HH) ? g_runcnt[e1] : 0;
    int s = c0 + c1;
    int incl = s;
#pragma unroll
    for (int o = 1; o < 32; o <<= 1) {
        int t = __shfl_up_sync(FULL, incl, o);
        if (lane >= o) incl += t;
    }
    if (lane == 31) swt[wid] = incl;
    __syncthreads();
    if (tid < 32) {
        int v = swt[tid], iv = v;
#pragma unroll
        for (int o = 1; o < 32; o <<= 1) {
            int t = __shfl_up_sync(FULL, iv, o);
            if (tid >= o) iv += t;
        }
        swt[tid] = iv - v;   // exclusive warp base
    }
    __syncthreads();
    int basep = swt[wid] + incl - s;
    soff[e0] = basep;
    soff[e1] = basep + c0;
    __syncthreads();

    int R = soff[HH];
    if (R > MAXC) R = MAXC;

    // copy runs to compact arrays + init parents
    for (int y = tid; y < HH; y += NTHR) {
        int off = soff[y], cnt = soff[y + 1] - off;
        for (int k = 0; k < cnt; k++) {
            int cid = off + k;
            if (cid >= MAXC) break;
            int sid = y * CAP + k;
            int se = g_rse[sid];
            cxse[cid]    = se;
            g_cy[cid]    = y;
            g_ctext[cid] = g_rtext[sid];
            g_cxmin[cid] = se & 0xffff;
            g_cxmax[cid] = se >> 16;
            g_cymax[cid] = y;
        }
    }
    for (int i = tid; i < R; i += NTHR) spar[i] = i;
    __syncthreads();

    // hierarchical union rounds: round r merges row-blocks of size 2^r
#pragma unroll
    for (int r = 0; r < 11; r++) {
        for (int m = tid; ; m += NTHR) {
            int b = (2 * m + 1) << r;
            if (b >= HH) break;
            int i = soff[b - 1], ie = soff[b];
            int j = soff[b],     je = soff[b + 1];
            if (ie > MAXC) ie = MAXC;
            if (je > MAXC) je = MAXC;
            while (i < ie && j < je) {
                int A = cxse[i], B = cxse[j];
                int axs = A & 0xffff, axe = A >> 16;
                int bxs = B & 0xffff, bxe = B >> 16;
                if (axs <= bxe && bxs <= axe) sunite(spar, i, j);
                if (axe < bxe) i++; else j++;
            }
        }
        __syncthreads();
    }

    // full compress (no more unions: plain stores safe)
    for (int i = tid; i < R; i += NTHR) {
        int f = i, n = spar[f];
        while (n != f) { f = n; n = spar[f]; }
        spar[i] = f;
    }
    __syncthreads();

    // fold run bboxes into roots
    for (int i = tid; i < R; i += NTHR) {
        int f = spar[i];
        if (f == i) continue;
        atomicMin(&g_cxmin[f], g_cxmin[i]);
        atomicMax(&g_cxmax[f], g_cxmax[i]);
        atomicMax(&g_cymax[f], g_cy[i]);
        if (g_ctext[i]) atomicMax(&g_ctext[f], 1);
    }
    __syncthreads();

    // emit roots
    for (int i = tid; i < R; i += NTHR) {
        if (spar[i] != i) continue;          // root = component min (y, xs) run
        int y = g_cy[i];
        int xs = cxse[i] & 0xffff;           // min flat index = y*WW + xs
        int h = g_cymax[i] - y;
        int w = g_cxmax[i] - g_cxmin[i];
        if (h > 4 && w > 4 && g_ctext[i]) {
            int flat = y * WW + xs;
            ((float4*)out)[flat] = make_float4((float)y, (float)g_cxmin[i],
                                               (float)h, (float)w);
            out[4 * NN + flat] = 1.0f;
        }
    }
}

extern "C" void kernel_launch(void* const* d_in, const int* in_sizes, int n_in,
                              void* d_out, int out_size) {
    const float* x = (const float*)d_in[0];
    float* out = (float*)d_out;
    int n4 = out_size / 4;
    cudaFuncSetAttribute(k_all, cudaFuncAttributeMaxDynamicSharedMemorySize, DYNSM);
    k_all<<<NBLK, NTHR, DYNSM>>>(x, out, n4, out_size);
}